// round 3
// baseline (speedup 1.0000x reference)
#include <cuda_runtime.h>
#include <math.h>
#include <float.h>

#define NB 4
#define NP 4096
#define NC 256
#define NK 16
#define NPTS (NB*NP)      /* 16384 */
#define NROWS (NPTS*NK)   /* 262144 */

// ---------------- scratch (device globals; no allocation) ----------------
__device__ float g_q [NPTS*NC];
__device__ float g_kf[NPTS*NC];
__device__ float g_vf[NPTS*NC];
__device__ int   g_idx[NROWS];
__device__ float g_u [NROWS*3];
__device__ float g_h [NROWS*NC];   // h, later reused for attn
__device__ float g_h2[NROWS*NC];
__device__ float g_bnd[6];         // scale[3], shift[3] for d-path BN
__device__ float g_partd[512*6];
__device__ float g_ps1[512*NC];
__device__ float g_pq1[512*NC];
__device__ float g_ps2[2048*NC];
__device__ float g_pq2[2048*NC];
__device__ float g_bn1[2*NC];
__device__ float g_bn2[2*NC];

// Bit-exact replication of the reference's fp32 rounding:
//   sq  = ((x*x + y*y) + z*z)            -- separate mul + sequential reduce
//   dot = fma(z,z', fma(y,y', x*x'))     -- K=3 gemm fma accumulation chain
//   d   = (sq_n + sq_m) - (2*dot)        -- elementwise, each op rounded
__device__ __forceinline__ float sq3_exact(float x, float y, float z){
    return __fadd_rn(__fadd_rn(__fmul_rn(x,x), __fmul_rn(y,y)), __fmul_rn(z,z));
}
__device__ __forceinline__ float dist_exact(float qx,float qy,float qz,float qw,
                                            float px,float py,float pz,float pw){
    float dot = __fmaf_rn(qz, pz, __fmaf_rn(qy, py, __fmul_rn(qx, px)));
    return __fsub_rn(__fadd_rn(qw, pw), __fmul_rn(2.0f, dot));
}

// ---------------- KNN: one warp per query, chunked smem points ----------------
__global__ __launch_bounds__(512) void knn_kernel(const float* __restrict__ xyz)
{
    constexpr int CH = 2048;
    __shared__ float4 pts[CH];
    int b = blockIdx.y;
    const float* xb = xyz + b*NP*3;
    int warp = threadIdx.x >> 5, lane = threadIdx.x & 31;
    int n = blockIdx.x*16 + warp;
    float qx = xb[n*3+0], qy = xb[n*3+1], qz = xb[n*3+2];
    float qw = sq3_exact(qx, qy, qz);
    float dl[NK]; int il[NK];
#pragma unroll
    for (int j=0;j<NK;j++){ dl[j]=FLT_MAX; il[j]=0x7fffffff; }

    for (int c0=0;c0<NP;c0+=CH){
        __syncthreads();
        for (int i=threadIdx.x;i<CH;i+=512){
            int m=c0+i;
            float x=xb[m*3],y=xb[m*3+1],z=xb[m*3+2];
            pts[i]=make_float4(x,y,z, sq3_exact(x,y,z));
        }
        __syncthreads();
        for (int i=lane;i<CH;i+=32){
            float4 p=pts[i];
            int m=c0+i;
            float d = dist_exact(qx,qy,qz,qw, p.x,p.y,p.z,p.w);
            if (d < dl[NK-1] || (d==dl[NK-1] && m<il[NK-1])){
                dl[NK-1]=d; il[NK-1]=m;
#pragma unroll
                for (int j=NK-1;j>0;j--){
                    bool sw = dl[j]<dl[j-1] || (dl[j]==dl[j-1] && il[j]<il[j-1]);
                    float t0 = sw? dl[j-1]:dl[j];
                    float t1 = sw? dl[j]:dl[j-1];
                    int   i0 = sw? il[j-1]:il[j];
                    int   i1 = sw? il[j]:il[j-1];
                    dl[j]=t0; dl[j-1]=t1; il[j]=i0; il[j-1]=i1;
                }
            }
        }
    }
    // warp-wide merge of 32 sorted lists -> global top-16
    for (int r=0;r<NK;r++){
        float cd = dl[0]; int ci = il[0];
        float rd = cd;    int ri = ci;
#pragma unroll
        for (int off=16; off>0; off>>=1){
            float od = __shfl_down_sync(0xffffffffu, rd, off);
            int   oi = __shfl_down_sync(0xffffffffu, ri, off);
            if (od<rd || (od==rd && oi<ri)){ rd=od; ri=oi; }
        }
        rd = __shfl_sync(0xffffffffu, rd, 0);
        ri = __shfl_sync(0xffffffffu, ri, 0);
        if (lane==0) g_idx[(b*NP+n)*NK + r] = ri;
        if (cd==rd && ci==ri){
#pragma unroll
            for (int j=0;j<NK-1;j++){ dl[j]=dl[j+1]; il[j]=il[j+1]; }
            dl[NK-1]=FLT_MAX; il[NK-1]=0x7fffffff;
        }
    }
}

// ---------------- d-path BN stats: t = rel@d1_w + d1_b, 3 channels ----------------
__global__ __launch_bounds__(256) void dstat_kernel(const float* __restrict__ xyz,
                                                    const float* __restrict__ d1w,
                                                    const float* __restrict__ d1b)
{
    float s[3]={0.f,0.f,0.f}, sq[3]={0.f,0.f,0.f};
    int stride = gridDim.x*blockDim.x;
    for (int it = blockIdx.x*blockDim.x+threadIdx.x; it < NROWS; it += stride){
        int pt = it >> 4;
        int b  = pt >> 12;
        int j  = g_idx[it];
        float r0 = xyz[pt*3+0] - xyz[(b*NP+j)*3+0];
        float r1 = xyz[pt*3+1] - xyz[(b*NP+j)*3+1];
        float r2 = xyz[pt*3+2] - xyz[(b*NP+j)*3+2];
#pragma unroll
        for (int d=0;d<3;d++){
            float t = r0*d1w[d] + r1*d1w[3+d] + r2*d1w[6+d] + d1b[d];
            s[d]+=t; sq[d]+=t*t;
        }
    }
    __shared__ float red[256];
    for (int q=0;q<6;q++){
        red[threadIdx.x] = (q<3)? s[q] : sq[q-3];
        __syncthreads();
        for (int st=128; st; st>>=1){
            if (threadIdx.x<st) red[threadIdx.x]+=red[threadIdx.x+st];
            __syncthreads();
        }
        if (threadIdx.x==0) g_partd[blockIdx.x*6+q]=red[0];
        __syncthreads();
    }
}

__global__ void dfin_kernel(const float* __restrict__ g, const float* __restrict__ beta)
{
    int d = threadIdx.x;
    if (d>=3) return;
    double s=0.0,q=0.0;
    for (int i=0;i<512;i++){ s+=g_partd[i*6+d]; q+=g_partd[i*6+3+d]; }
    double m = s/(double)NROWS;
    double v = q/(double)NROWS - m*m;
    double sc = (double)g[d] / sqrt(v+1e-5);
    g_bnd[d]   = (float)sc;
    g_bnd[3+d] = (float)((double)beta[d] - m*sc);
}

// ---------------- generic fp32 GEMM: C[MxN] = f(A)[Mx256] @ B[256xN] + bias ----------------
// BNRELU: A element -> max(0, a*bnp[c]+bnp[256+c]).  STATS: per-column sum/sumsq partials.
template<bool BNRELU, bool STATS>
__global__ __launch_bounds__(256) void gemm_kernel(
    const float* __restrict__ A, const float* __restrict__ Bm,
    const float* __restrict__ bias, float* __restrict__ C,
    const float* __restrict__ bnp, float* __restrict__ psum, float* __restrict__ psq)
{
    __shared__ __align__(16) float As[8][132];
    __shared__ __align__(16) float Bs[8][132];
    __shared__ float red[16][128];
    int tid = threadIdx.x;
    int tx = tid & 15, ty = tid >> 4;
    int mblk = blockIdx.x, nblk = blockIdx.y;
    int arow = tid >> 1, acg = (tid & 1)*4;
    int brow = tid >> 5, bcol = (tid & 31)*4;
    const float* Aptr = A + (size_t)(mblk*128 + arow)*256;
    const float* Bptr = Bm + nblk*128;
    float acc[8][8];
#pragma unroll
    for (int i=0;i<8;i++)
#pragma unroll
        for (int j=0;j<8;j++) acc[i][j]=0.f;

    for (int k0=0;k0<256;k0+=8){
        float4 av = *(const float4*)(Aptr + k0 + acg);
        if (BNRELU){
            int c = k0+acg;
            av.x = fmaxf(0.f, fmaf(av.x, bnp[c+0], bnp[256+c+0]));
            av.y = fmaxf(0.f, fmaf(av.y, bnp[c+1], bnp[256+c+1]));
            av.z = fmaxf(0.f, fmaf(av.z, bnp[c+2], bnp[256+c+2]));
            av.w = fmaxf(0.f, fmaf(av.w, bnp[c+3], bnp[256+c+3]));
        }
        As[acg+0][arow]=av.x; As[acg+1][arow]=av.y;
        As[acg+2][arow]=av.z; As[acg+3][arow]=av.w;
        float4 bv = *(const float4*)(Bptr + (k0+brow)*256 + bcol);
        *(float4*)&Bs[brow][bcol] = bv;
        __syncthreads();
#pragma unroll
        for (int kk=0;kk<8;kk++){
            float a[8], bb[8];
            *(float4*)(a)    = *(const float4*)&As[kk][ty*8];
            *(float4*)(a+4)  = *(const float4*)&As[kk][ty*8+4];
            *(float4*)(bb)   = *(const float4*)&Bs[kk][tx*8];
            *(float4*)(bb+4) = *(const float4*)&Bs[kk][tx*8+4];
#pragma unroll
            for (int i=0;i<8;i++)
#pragma unroll
                for (int j=0;j<8;j++) acc[i][j] = fmaf(a[i], bb[j], acc[i][j]);
        }
        __syncthreads();
    }

    float bvr[8];
#pragma unroll
    for (int j=0;j<8;j++) bvr[j] = bias[nblk*128 + tx*8 + j];
    float cs[8], cq[8];
#pragma unroll
    for (int j=0;j<8;j++){ cs[j]=0.f; cq[j]=0.f; }
#pragma unroll
    for (int i=0;i<8;i++){
        int row = mblk*128 + ty*8 + i;
        float o[8];
#pragma unroll
        for (int j=0;j<8;j++){
            float v = acc[i][j] + bvr[j];
            o[j]=v;
            if (STATS){ cs[j]+=v; cq[j]+=v*v; }
        }
        float* cp = C + (size_t)row*256 + nblk*128 + tx*8;
        *(float4*)cp     = make_float4(o[0],o[1],o[2],o[3]);
        *(float4*)(cp+4) = make_float4(o[4],o[5],o[6],o[7]);
    }

    if (STATS){
#pragma unroll
        for (int j=0;j<8;j++) red[ty][tx*8+j]=cs[j];
        __syncthreads();
        for (int st=8; st>0; st>>=1){
            if (ty<st){
#pragma unroll
                for (int j=0;j<8;j++) red[ty][tx*8+j]+=red[ty+st][tx*8+j];
            }
            __syncthreads();
        }
        if (ty==0){
#pragma unroll
            for (int j=0;j<8;j++) psum[mblk*256 + nblk*128 + tx*8 + j] = red[0][tx*8+j];
        }
        __syncthreads();
#pragma unroll
        for (int j=0;j<8;j++) red[ty][tx*8+j]=cq[j];
        __syncthreads();
        for (int st=8; st>0; st>>=1){
            if (ty<st){
#pragma unroll
                for (int j=0;j<8;j++) red[ty][tx*8+j]+=red[ty+st][tx*8+j];
            }
            __syncthreads();
        }
        if (ty==0){
#pragma unroll
            for (int j=0;j<8;j++) psq[mblk*256 + nblk*128 + tx*8 + j] = red[0][tx*8+j];
        }
    }
}

// ---------------- finalize per-channel BN over 256 channels ----------------
__global__ __launch_bounds__(256) void bnfin_kernel(const float* __restrict__ psum,
                                                    const float* __restrict__ psq, int P,
                                                    const float* __restrict__ g,
                                                    const float* __restrict__ beta,
                                                    float* __restrict__ outp)
{
    int c = threadIdx.x;
    double s=0.0,q=0.0;
    for (int i=0;i<P;i++){ s+=psum[i*NC+c]; q+=psq[i*NC+c]; }
    double m = s/(double)NROWS;
    double v = q/(double)NROWS - m*m;
    double sc = (double)g[c] / sqrt(v+1e-5);
    outp[c]    = (float)sc;
    outp[NC+c] = (float)((double)beta[c] - m*sc);
}

// ---------------- h producer: h = q - k[idx] + pos_enc; fused channel stats ----------------
__global__ __launch_bounds__(256) void hprod_kernel(
    const float* __restrict__ xyz, const float* __restrict__ d1w, const float* __restrict__ d1b,
    const float* __restrict__ d2w, const float* __restrict__ d2b)
{
    __shared__ float su[NK*3];
    __shared__ int   sj[NK];
    int c = threadIdx.x;
    float d2c0 = d2w[c], d2c1 = d2w[256+c], d2c2 = d2w[512+c], d2bc = d2b[c];
    float s=0.f, q=0.f;
    for (int pp=0; pp<32; pp++){
        int pt = blockIdx.x*32 + pp;
        int b  = pt >> 12;
        if (c < NK){
            int k = c;
            int j = g_idx[pt*NK+k];
            sj[k]=j;
            float r0 = xyz[pt*3+0]-xyz[(b*NP+j)*3+0];
            float r1 = xyz[pt*3+1]-xyz[(b*NP+j)*3+1];
            float r2 = xyz[pt*3+2]-xyz[(b*NP+j)*3+2];
#pragma unroll
            for (int d=0;d<3;d++){
                float t  = r0*d1w[d] + r1*d1w[3+d] + r2*d1w[6+d] + d1b[d];
                float uu = fmaxf(0.f, fmaf(t, g_bnd[d], g_bnd[3+d]));
                su[k*3+d]=uu;
                g_u[(pt*NK+k)*3+d]=uu;
            }
        }
        __syncthreads();
        float qv = g_q[pt*NC + c];
#pragma unroll
        for (int k=0;k<NK;k++){
            int j = sj[k];
            float kv = g_kf[(b*NP+j)*NC + c];
            float pe = su[k*3]*d2c0 + su[k*3+1]*d2c1 + su[k*3+2]*d2c2 + d2bc;
            float h = qv - kv + pe;
            g_h[(size_t)(pt*NK+k)*NC + c] = h;
            s += h; q += h*h;
        }
        __syncthreads();
    }
    g_ps1[blockIdx.x*NC+c]=s;
    g_pq1[blockIdx.x*NC+c]=q;
}

// ---------------- softmax over K + weighted gather output ----------------
__global__ __launch_bounds__(256) void out_kernel(
    float* __restrict__ out, const float* __restrict__ d2w, const float* __restrict__ d2b)
{
    __shared__ float su[NK*3];
    __shared__ int   sj[NK];
    int pt = blockIdx.x;
    int b  = pt >> 12;
    int a  = threadIdx.x;
    if (a < NK)   sj[a] = g_idx[pt*NK+a];
    if (a < NK*3) su[a] = g_u[pt*NK*3 + a];
    __syncthreads();
    float d0=d2w[a], d1=d2w[256+a], d2=d2w[512+a], db=d2b[a];
    float e[NK];
    float mx = -FLT_MAX;
#pragma unroll
    for (int k=0;k<NK;k++){
        float x = g_h[(size_t)(pt*NK+k)*NC + a];   // attn logits (g_h reused)
        e[k]=x; mx = fmaxf(mx,x);
    }
    float sm=0.f;
#pragma unroll
    for (int k=0;k<NK;k++){ e[k]=expf(e[k]-mx); sm+=e[k]; }
    float inv = 1.f/sm;
    float o=0.f;
#pragma unroll
    for (int k=0;k<NK;k++){
        int j = sj[k];
        float v  = g_vf[(b*NP+j)*NC + a];
        float pe = su[k*3]*d0 + su[k*3+1]*d1 + su[k*3+2]*d2 + db;
        o += e[k]*inv*(v+pe);
    }
    out[pt*NC + a] = o;
}

// ---------------- host launcher (graph-capturable, allocation-free) ----------------
extern "C" void kernel_launch(void* const* d_in, const int* in_sizes, int n_in,
                              void* d_out, int out_size)
{
    const float* xyz  = (const float*)d_in[0];
    const float* feat = (const float*)d_in[1];
    const float* wq   = (const float*)d_in[2];  const float* bq  = (const float*)d_in[3];
    const float* wk   = (const float*)d_in[4];  const float* bk  = (const float*)d_in[5];
    const float* wv   = (const float*)d_in[6];  const float* bv  = (const float*)d_in[7];
    const float* d1w  = (const float*)d_in[8];  const float* d1b = (const float*)d_in[9];
    const float* bndg = (const float*)d_in[10]; const float* bndb= (const float*)d_in[11];
    const float* d2w  = (const float*)d_in[12]; const float* d2b = (const float*)d_in[13];
    const float* g1g  = (const float*)d_in[14]; const float* g1bt= (const float*)d_in[15];
    const float* g1w  = (const float*)d_in[16]; const float* g1b = (const float*)d_in[17];
    const float* g2g  = (const float*)d_in[18]; const float* g2bt= (const float*)d_in[19];
    const float* g2w  = (const float*)d_in[20]; const float* g2b = (const float*)d_in[21];
    float* out = (float*)d_out;

    float *p_q,*p_kf,*p_vf,*p_h,*p_h2,*p_bn1,*p_bn2,*p_ps1,*p_pq1,*p_ps2,*p_pq2;
    cudaGetSymbolAddress((void**)&p_q,  g_q);
    cudaGetSymbolAddress((void**)&p_kf, g_kf);
    cudaGetSymbolAddress((void**)&p_vf, g_vf);
    cudaGetSymbolAddress((void**)&p_h,  g_h);
    cudaGetSymbolAddress((void**)&p_h2, g_h2);
    cudaGetSymbolAddress((void**)&p_bn1,g_bn1);
    cudaGetSymbolAddress((void**)&p_bn2,g_bn2);
    cudaGetSymbolAddress((void**)&p_ps1,g_ps1);
    cudaGetSymbolAddress((void**)&p_pq1,g_pq1);
    cudaGetSymbolAddress((void**)&p_ps2,g_ps2);
    cudaGetSymbolAddress((void**)&p_pq2,g_pq2);

    // 1. KNN indices
    knn_kernel<<<dim3(NP/16, NB), 512>>>(xyz);
    // 2. d-path BN stats + finalize
    dstat_kernel<<<512,256>>>(xyz, d1w, d1b);
    dfin_kernel<<<1,32>>>(bndg, bndb);
    // 3. q / k / v projections
    gemm_kernel<false,false><<<dim3(NPTS/128,2),256>>>(feat, wq, bq, p_q,  nullptr, nullptr, nullptr);
    gemm_kernel<false,false><<<dim3(NPTS/128,2),256>>>(feat, wk, bk, p_kf, nullptr, nullptr, nullptr);
    gemm_kernel<false,false><<<dim3(NPTS/128,2),256>>>(feat, wv, bv, p_vf, nullptr, nullptr, nullptr);
    // 4. h = q - k[idx] + pos_enc (stores u, fused bn1 stats)
    hprod_kernel<<<512,256>>>(xyz, d1w, d1b, d2w, d2b);
    bnfin_kernel<<<1,256>>>(p_ps1, p_pq1, 512, g1g, g1bt, p_bn1);
    // 5. gamma layer 1: relu(bn1(h)) @ g1_w + g1_b  (fused bn2 stats)
    gemm_kernel<true,true><<<dim3(NROWS/128,2),256>>>(p_h, g1w, g1b, p_h2, p_bn1, p_ps2, p_pq2);
    bnfin_kernel<<<1,256>>>(p_ps2, p_pq2, 2048, g2g, g2bt, p_bn2);
    // 6. gamma layer 2: relu(bn2(h2)) @ g2_w + g2_b -> attn logits (into g_h)
    gemm_kernel<true,false><<<dim3(NROWS/128,2),256>>>(p_h2, g2w, g2b, p_h, p_bn2, nullptr, nullptr);
    // 7. softmax over K + weighted (v + pos_enc) sum
    out_kernel<<<NPTS,256>>>(out, d2w, d2b);
}